// round 1
// baseline (speedup 1.0000x reference)
#include <cuda_runtime.h>
#include <math.h>

#define B_  4
#define S_  2048
#define D_  1024
#define H_  16
#define HD  64
#define ROWS (B_*S_)        // 8192
#define SCALE 0.125f        // 64^-0.5

// ---------------- scratch (device globals; no allocations) ----------------
__device__ float g_q[(size_t)B_*H_*S_*HD];     // [B*H, S, 64]
__device__ float g_k[(size_t)B_*H_*S_*HD];
__device__ float g_v[(size_t)B_*H_*S_*HD];
__device__ float g_attn[(size_t)ROWS*D_];      // [B*S, D]

// ---------------- GEMM: C = A[M,K] @ W[K,N] + bias ------------------------
// Tiles 64x64x16, 256 threads, 4x4 micro-tile per thread.
// SCATTER==1: write into g_q/g_k/g_v with [B,H,S,d] layout (QKV pass).
// A_GATTN==1: read A from g_attn (proj pass).
template<int SCATTER, int A_GATTN>
__global__ void __launch_bounds__(256) gemm_kernel(
    const float* __restrict__ Ain, const float* __restrict__ W,
    const float* __restrict__ bias, float* __restrict__ C,
    int M, int N, int K)
{
    const float* A = A_GATTN ? g_attn : Ain;

    __shared__ float As[16][64];   // transposed: As[k][m]
    __shared__ float Bs[16][64];   // Bs[k][n]

    const int tid = threadIdx.x;
    const int ty  = tid >> 4;       // 0..15
    const int tx  = tid & 15;       // 0..15
    const int m0  = blockIdx.y * 64;
    const int n0  = blockIdx.x * 64;

    // A-load mapping: one float4 per thread per k-step
    const int arow = tid >> 2;          // 0..63
    const int ac4  = (tid & 3) * 4;     // 0,4,8,12
    // B-load mapping
    const int brow = tid >> 4;          // 0..15
    const int bc4  = (tid & 15) * 4;    // 0..60

    float acc[4][4];
    #pragma unroll
    for (int i = 0; i < 4; i++)
        #pragma unroll
        for (int j = 0; j < 4; j++) acc[i][j] = 0.f;

    for (int k0 = 0; k0 < K; k0 += 16) {
        float4 av = *(const float4*)&A[(size_t)(m0 + arow) * K + k0 + ac4];
        As[ac4 + 0][arow] = av.x;
        As[ac4 + 1][arow] = av.y;
        As[ac4 + 2][arow] = av.z;
        As[ac4 + 3][arow] = av.w;
        float4 bv = *(const float4*)&W[(size_t)(k0 + brow) * N + n0 + bc4];
        *(float4*)&Bs[brow][bc4] = bv;
        __syncthreads();

        #pragma unroll
        for (int kk = 0; kk < 16; kk++) {
            float ra[4], rb[4];
            #pragma unroll
            for (int i = 0; i < 4; i++) ra[i] = As[kk][ty * 4 + i];
            #pragma unroll
            for (int j = 0; j < 4; j++) rb[j] = Bs[kk][tx * 4 + j];
            #pragma unroll
            for (int i = 0; i < 4; i++)
                #pragma unroll
                for (int j = 0; j < 4; j++)
                    acc[i][j] = fmaf(ra[i], rb[j], acc[i][j]);
        }
        __syncthreads();
    }

    #pragma unroll
    for (int i = 0; i < 4; i++) {
        const int r = m0 + ty * 4 + i;
        #pragma unroll
        for (int j = 0; j < 4; j++) {
            const int c = n0 + tx * 4 + j;
            float v = acc[i][j] + bias[c];
            if (SCATTER) {
                const int sect = c >> 10;        // 0=q 1=k 2=v
                const int rem  = c & 1023;
                const int h    = rem >> 6;
                const int dd   = rem & 63;
                const int b    = r >> 11;        // /2048
                const int s    = r & 2047;
                const size_t idx = (((size_t)(b * H_ + h) * S_) + s) * HD + dd;
                float* dst = (sect == 0) ? g_q : (sect == 1) ? g_k : g_v;
                dst[idx] = v;
            } else {
                C[(size_t)r * N + c] = v;
            }
        }
    }
}

// ---------------- Flash attention ------------------------------------------
// Block: 256 threads = 16x16; handles 64 query rows of one (b,h).
// Iterates over 64-key tiles with online softmax.
#define QPAD 65
#define ATTN_SMEM (4 * 64 * QPAD * (int)sizeof(float))   // 66560 B

__global__ void __launch_bounds__(256) attn_kernel()
{
    extern __shared__ float sm[];
    float* Qs = sm;                  // [64][65]
    float* Ks = Qs + 64 * QPAD;
    float* Vs = Ks + 64 * QPAD;
    float* Ps = Vs + 64 * QPAD;

    const int tid = threadIdx.x;
    const int ty  = tid >> 4;
    const int tx  = tid & 15;
    const int q0  = blockIdx.x * 64;
    const int bh  = blockIdx.y;              // b*H + h

    const float* Qb = g_q + (size_t)bh * S_ * HD;
    const float* Kb = g_k + (size_t)bh * S_ * HD;
    const float* Vb = g_v + (size_t)bh * S_ * HD;

    // Load Q tile: 64x64 floats; each thread 4 float4
    const int lr = tid >> 2;             // 0..63
    const int lc = (tid & 3) * 16;       // 0,16,32,48
    #pragma unroll
    for (int t = 0; t < 4; t++) {
        float4 v = *(const float4*)&Qb[(size_t)(q0 + lr) * HD + lc + t * 4];
        Qs[lr * QPAD + lc + t * 4 + 0] = v.x;
        Qs[lr * QPAD + lc + t * 4 + 1] = v.y;
        Qs[lr * QPAD + lc + t * 4 + 2] = v.z;
        Qs[lr * QPAD + lc + t * 4 + 3] = v.w;
    }

    float m_i[4], l_i[4], acc[4][4];
    #pragma unroll
    for (int i = 0; i < 4; i++) {
        m_i[i] = -INFINITY; l_i[i] = 0.f;
        #pragma unroll
        for (int j = 0; j < 4; j++) acc[i][j] = 0.f;
    }

    for (int k0 = 0; k0 < S_; k0 += 64) {
        // Load K,V tiles
        #pragma unroll
        for (int t = 0; t < 4; t++) {
            float4 kv = *(const float4*)&Kb[(size_t)(k0 + lr) * HD + lc + t * 4];
            Ks[lr * QPAD + lc + t * 4 + 0] = kv.x;
            Ks[lr * QPAD + lc + t * 4 + 1] = kv.y;
            Ks[lr * QPAD + lc + t * 4 + 2] = kv.z;
            Ks[lr * QPAD + lc + t * 4 + 3] = kv.w;
            float4 vv = *(const float4*)&Vb[(size_t)(k0 + lr) * HD + lc + t * 4];
            Vs[lr * QPAD + lc + t * 4 + 0] = vv.x;
            Vs[lr * QPAD + lc + t * 4 + 1] = vv.y;
            Vs[lr * QPAD + lc + t * 4 + 2] = vv.z;
            Vs[lr * QPAD + lc + t * 4 + 3] = vv.w;
        }
        __syncthreads();

        // Scores: sc[i][j] = Q(row ty*4+i) . K(row tx*4+j)
        float sc[4][4];
        #pragma unroll
        for (int i = 0; i < 4; i++)
            #pragma unroll
            for (int j = 0; j < 4; j++) sc[i][j] = 0.f;

        #pragma unroll 8
        for (int kk = 0; kk < 64; kk++) {
            float ra[4], rb[4];
            #pragma unroll
            for (int i = 0; i < 4; i++) ra[i] = Qs[(ty * 4 + i) * QPAD + kk];
            #pragma unroll
            for (int j = 0; j < 4; j++) rb[j] = Ks[(tx * 4 + j) * QPAD + kk];
            #pragma unroll
            for (int i = 0; i < 4; i++)
                #pragma unroll
                for (int j = 0; j < 4; j++)
                    sc[i][j] = fmaf(ra[i], rb[j], sc[i][j]);
        }

        // Online softmax per query row (rows owned by the 16 tx-lanes jointly)
        #pragma unroll
        for (int i = 0; i < 4; i++) {
            float mx = fmaxf(fmaxf(sc[i][0], sc[i][1]), fmaxf(sc[i][2], sc[i][3])) * SCALE;
            #pragma unroll
            for (int off = 8; off >= 1; off >>= 1)
                mx = fmaxf(mx, __shfl_xor_sync(0xFFFFFFFFu, mx, off, 16));
            const float newm = fmaxf(m_i[i], mx);
            float rsum = 0.f;
            #pragma unroll
            for (int j = 0; j < 4; j++) {
                float p = __expf(sc[i][j] * SCALE - newm);
                sc[i][j] = p;            // reuse as P
                rsum += p;
            }
            #pragma unroll
            for (int off = 8; off >= 1; off >>= 1)
                rsum += __shfl_xor_sync(0xFFFFFFFFu, rsum, off, 16);
            const float factor = __expf(m_i[i] - newm);
            l_i[i] = l_i[i] * factor + rsum;
            m_i[i] = newm;
            #pragma unroll
            for (int j = 0; j < 4; j++) acc[i][j] *= factor;
        }

        // Store P to smem
        #pragma unroll
        for (int i = 0; i < 4; i++)
            #pragma unroll
            for (int j = 0; j < 4; j++)
                Ps[(ty * 4 + i) * QPAD + tx * 4 + j] = sc[i][j];
        __syncthreads();

        // acc += P(row) @ V
        #pragma unroll 8
        for (int kk = 0; kk < 64; kk++) {
            float rp[4], rv[4];
            #pragma unroll
            for (int i = 0; i < 4; i++) rp[i] = Ps[(ty * 4 + i) * QPAD + kk];
            #pragma unroll
            for (int j = 0; j < 4; j++) rv[j] = Vs[kk * QPAD + tx * 4 + j];
            #pragma unroll
            for (int i = 0; i < 4; i++)
                #pragma unroll
                for (int j = 0; j < 4; j++)
                    acc[i][j] = fmaf(rp[i], rv[j], acc[i][j]);
        }
        __syncthreads();
    }

    // Write out: g_attn[b][s][h*64+dd]
    const int b = bh >> 4;
    const int h = bh & 15;
    #pragma unroll
    for (int i = 0; i < 4; i++) {
        const int q = q0 + ty * 4 + i;
        const float inv = 1.f / l_i[i];
        #pragma unroll
        for (int j = 0; j < 4; j++) {
            const int dd = tx * 4 + j;
            g_attn[((size_t)(b * S_ + q)) * D_ + h * HD + dd] = acc[i][j] * inv;
        }
    }
}

// ---------------- launch ----------------------------------------------------
extern "C" void kernel_launch(void* const* d_in, const int* in_sizes, int n_in,
                              void* d_out, int out_size)
{
    const float* x      = (const float*)d_in[0];
    const float* W_qkv  = (const float*)d_in[1];
    const float* b_qkv  = (const float*)d_in[2];
    const float* W_proj = (const float*)d_in[3];
    const float* b_proj = (const float*)d_in[4];
    float* out = (float*)d_out;

    cudaFuncSetAttribute(attn_kernel, cudaFuncAttributeMaxDynamicSharedMemorySize, ATTN_SMEM);

    // 1) QKV GEMM + scatter into [B,H,S,d]
    gemm_kernel<1, 0><<<dim3(3 * D_ / 64, ROWS / 64), 256>>>(
        x, W_qkv, b_qkv, nullptr, ROWS, 3 * D_, D_);

    // 2) Flash attention
    attn_kernel<<<dim3(S_ / 64, B_ * H_), 256, ATTN_SMEM>>>();

    // 3) Output projection
    gemm_kernel<0, 1><<<dim3(D_ / 64, ROWS / 64), 256>>>(
        nullptr, W_proj, b_proj, out, ROWS, D_, D_);
}

// round 2
// speedup vs baseline: 2.3884x; 2.3884x over previous
#include <cuda_runtime.h>
#include <math.h>
#include <stdint.h>

#define B_  4
#define S_  2048
#define D_  1024
#define H_  16
#define HD  64
#define ROWS (B_*S_)        // 8192
#define SCALE 0.125f        // 64^-0.5

// ---------------- scratch (device globals; no allocations) ----------------
__device__ float g_q[(size_t)B_*H_*S_*HD];     // [B*H, S, 64]  (pre-scaled, tf32)
__device__ float g_k[(size_t)B_*H_*S_*HD];     // tf32-rounded
__device__ float g_v[(size_t)B_*H_*S_*HD];     // tf32-rounded
__device__ float g_attn[(size_t)ROWS*D_];      // [B*S, D] fp32

// ---------------- helpers ---------------------------------------------------
__device__ __forceinline__ float f2tf(float x) {
    uint32_t u; asm("cvt.rna.tf32.f32 %0, %1;" : "=r"(u) : "f"(x));
    return __uint_as_float(u);
}

__device__ __forceinline__ void mma_m16n8k8(float d[4], const uint32_t a[4],
                                            const uint32_t b[2], const float c[4]) {
    asm volatile(
        "mma.sync.aligned.m16n8k8.row.col.f32.tf32.tf32.f32 "
        "{%0,%1,%2,%3}, {%4,%5,%6,%7}, {%8,%9}, {%10,%11,%12,%13};"
        : "=f"(d[0]), "=f"(d[1]), "=f"(d[2]), "=f"(d[3])
        : "r"(a[0]), "r"(a[1]), "r"(a[2]), "r"(a[3]),
          "r"(b[0]), "r"(b[1]),
          "f"(c[0]), "f"(c[1]), "f"(c[2]), "f"(c[3]));
}

// ---------------- tensor-core GEMM: C = A[M,K] @ W[K,N] + bias --------------
// 128x128 block tile, BK=16, 256 threads (8 warps, 2x4), warp tile 64x32.
#define BM 128
#define BN 128
#define BK 16
#define LA 136   // As row pitch (conflict-free frag loads)
#define LB 136

template<int SCATTER, int A_GATTN>
__global__ void __launch_bounds__(256, 2) gemm_tc(
    const float* __restrict__ Ain, const float* __restrict__ W,
    const float* __restrict__ bias, float* __restrict__ C,
    int M, int N, int K)
{
    const float* A = A_GATTN ? g_attn : Ain;

    __shared__ float As[BK * LA];   // As[k*LA + m]
    __shared__ float Bs[BK * LB];   // Bs[k*LB + n]

    const int tid  = threadIdx.x;
    const int lane = tid & 31;
    const int wid  = tid >> 5;
    const int g    = lane >> 2;     // 0..7
    const int t    = lane & 3;      // 0..3
    const int wm   = (wid & 1) * 64;
    const int wn   = (wid >> 1) * 32;
    const int m0   = blockIdx.y * BM;
    const int n0   = blockIdx.x * BN;

    // A staging: 2 float4/thread, rows (tid>>2)+{0,64}, k4=(tid&3)*4
    const int ar = tid >> 2;
    const int ak = (tid & 3) * 4;
    // B staging: rows k=(tid>>5)+{0,8}, n4=(tid&31)*4
    const int bk = tid >> 5;
    const int bn = (tid & 31) * 4;

    float acc[4][4][4];
    #pragma unroll
    for (int mi = 0; mi < 4; mi++)
        #pragma unroll
        for (int ni = 0; ni < 4; ni++)
            #pragma unroll
            for (int j = 0; j < 4; j++) acc[mi][ni][j] = 0.f;

    for (int k0 = 0; k0 < K; k0 += BK) {
        #pragma unroll
        for (int p = 0; p < 2; p++) {
            float4 v = *(const float4*)&A[(size_t)(m0 + ar + p * 64) * K + k0 + ak];
            const int mcol = ar + p * 64;
            As[(ak + 0) * LA + mcol] = f2tf(v.x);
            As[(ak + 1) * LA + mcol] = f2tf(v.y);
            As[(ak + 2) * LA + mcol] = f2tf(v.z);
            As[(ak + 3) * LA + mcol] = f2tf(v.w);
        }
        #pragma unroll
        for (int p = 0; p < 2; p++) {
            float4 v = *(const float4*)&W[(size_t)(k0 + bk + p * 8) * N + n0 + bn];
            float* dst = &Bs[(bk + p * 8) * LB + bn];
            dst[0] = f2tf(v.x); dst[1] = f2tf(v.y);
            dst[2] = f2tf(v.z); dst[3] = f2tf(v.w);
        }
        __syncthreads();

        #pragma unroll
        for (int ks = 0; ks < 2; ks++) {
            const int kb = ks * 8;
            uint32_t af[4][4], bf[4][2];
            #pragma unroll
            for (int mi = 0; mi < 4; mi++) {
                const int mr = wm + mi * 16;
                af[mi][0] = __float_as_uint(As[(kb + t    ) * LA + mr + g    ]);
                af[mi][1] = __float_as_uint(As[(kb + t    ) * LA + mr + g + 8]);
                af[mi][2] = __float_as_uint(As[(kb + t + 4) * LA + mr + g    ]);
                af[mi][3] = __float_as_uint(As[(kb + t + 4) * LA + mr + g + 8]);
            }
            #pragma unroll
            for (int ni = 0; ni < 4; ni++) {
                const int nc = wn + ni * 8;
                bf[ni][0] = __float_as_uint(Bs[(kb + t    ) * LB + nc + g]);
                bf[ni][1] = __float_as_uint(Bs[(kb + t + 4) * LB + nc + g]);
            }
            #pragma unroll
            for (int mi = 0; mi < 4; mi++)
                #pragma unroll
                for (int ni = 0; ni < 4; ni++)
                    mma_m16n8k8(acc[mi][ni], af[mi], bf[ni], acc[mi][ni]);
        }
        __syncthreads();
    }

    // epilogue
    #pragma unroll
    for (int mi = 0; mi < 4; mi++) {
        const int r0 = m0 + wm + mi * 16 + g;
        #pragma unroll
        for (int ni = 0; ni < 4; ni++) {
            const int c0 = n0 + wn + ni * 8 + 2 * t;
            float v0 = acc[mi][ni][0] + bias[c0];
            float v1 = acc[mi][ni][1] + bias[c0 + 1];
            float v2 = acc[mi][ni][2] + bias[c0];
            float v3 = acc[mi][ni][3] + bias[c0 + 1];
            if (SCATTER) {
                // c -> (sect, h, dd); r -> (b, s). Store tf32-rounded; Q pre-scaled.
                const int sect = c0 >> 10;
                const int rem  = c0 & 1023;
                const int h    = rem >> 6;
                const int dd   = rem & 63;
                float* dst = (sect == 0) ? g_q : (sect == 1) ? g_k : g_v;
                const float sc = (sect == 0) ? SCALE : 1.f;
                {
                    const int b = r0 >> 11, s = r0 & 2047;
                    float* p = &dst[(((size_t)(b * H_ + h) * S_) + s) * HD + dd];
                    p[0] = f2tf(v0 * sc);
                    p[1] = f2tf(v1 * sc);
                }
                {
                    const int r1 = r0 + 8;
                    const int b = r1 >> 11, s = r1 & 2047;
                    float* p = &dst[(((size_t)(b * H_ + h) * S_) + s) * HD + dd];
                    p[0] = f2tf(v2 * sc);
                    p[1] = f2tf(v3 * sc);
                }
            } else {
                *(float2*)&C[(size_t)r0 * N + c0]       = make_float2(v0, v1);
                *(float2*)&C[(size_t)(r0 + 8) * N + c0] = make_float2(v2, v3);
            }
        }
    }
}

// ---------------- flash attention (tensor core) -----------------------------
// Block: 128 threads (4 warps); 64 query rows (16 per warp); 64-key tiles.
#define LK 68
#define LV 72
#define LP 68
#define ATTN_SMEM ((64*LK + 64*LV + 4*16*LP) * (int)sizeof(float))  // 53248

__global__ void __launch_bounds__(128) attn_tc()
{
    extern __shared__ float sm[];
    float* Ks = sm;                         // [64][LK] (also Q staging)
    float* Vs = Ks + 64 * LK;               // [64][LV]
    float* Ps = Vs + 64 * LV;               // [4][16][LP] per-warp

    const int tid  = threadIdx.x;
    const int lane = tid & 31;
    const int wid  = tid >> 5;
    const int g    = lane >> 2;
    const int t    = lane & 3;
    const int q0   = blockIdx.x * 64;
    const int bh   = blockIdx.y;

    const float* Qb = g_q + (size_t)bh * S_ * HD;
    const float* Kb = g_k + (size_t)bh * S_ * HD;
    const float* Vb = g_v + (size_t)bh * S_ * HD;

    // staging mapping: row = tid>>1 (0..63), half = (tid&1)*32, 8 float4/thread
    const int sr = tid >> 1;
    const int sc = (tid & 1) * 32;

    // ---- stage Q into Ks, then lift to register fragments (already tf32+scaled)
    #pragma unroll
    for (int i = 0; i < 8; i++) {
        float4 v = *(const float4*)&Qb[(size_t)(q0 + sr) * HD + sc + i * 4];
        float* d = &Ks[sr * LK + sc + i * 4];
        d[0] = v.x; d[1] = v.y; d[2] = v.z; d[3] = v.w;
    }
    __syncthreads();

    uint32_t qf[8][4];
    const int qr = wid * 16;
    #pragma unroll
    for (int kc = 0; kc < 8; kc++) {
        qf[kc][0] = __float_as_uint(Ks[(qr + g    ) * LK + kc * 8 + t    ]);
        qf[kc][1] = __float_as_uint(Ks[(qr + g + 8) * LK + kc * 8 + t    ]);
        qf[kc][2] = __float_as_uint(Ks[(qr + g    ) * LK + kc * 8 + t + 4]);
        qf[kc][3] = __float_as_uint(Ks[(qr + g + 8) * LK + kc * 8 + t + 4]);
    }
    __syncthreads();

    float oacc[8][4];
    #pragma unroll
    for (int ni = 0; ni < 8; ni++)
        #pragma unroll
        for (int j = 0; j < 4; j++) oacc[ni][j] = 0.f;
    float m0v = -INFINITY, m1v = -INFINITY, l0v = 0.f, l1v = 0.f;

    float* Pw = Ps + wid * 16 * LP;

    for (int kt = 0; kt < S_ / 64; kt++) {
        const int kb = kt * 64;
        // ---- stage K, V tiles (already tf32 in gmem)
        #pragma unroll
        for (int i = 0; i < 8; i++) {
            float4 v = *(const float4*)&Kb[(size_t)(kb + sr) * HD + sc + i * 4];
            float* dk = &Ks[sr * LK + sc + i * 4];
            dk[0] = v.x; dk[1] = v.y; dk[2] = v.z; dk[3] = v.w;
            float4 w = *(const float4*)&Vb[(size_t)(kb + sr) * HD + sc + i * 4];
            float* dv = &Vs[sr * LV + sc + i * 4];
            dv[0] = w.x; dv[1] = w.y; dv[2] = w.z; dv[3] = w.w;
        }
        __syncthreads();

        // ---- S = Q @ K^T  (16 q-rows x 64 keys per warp)
        float sf[8][4];
        #pragma unroll
        for (int ni = 0; ni < 8; ni++)
            #pragma unroll
            for (int j = 0; j < 4; j++) sf[ni][j] = 0.f;

        #pragma unroll
        for (int kc = 0; kc < 8; kc++) {
            #pragma unroll
            for (int ni = 0; ni < 8; ni++) {
                uint32_t bb[2];
                bb[0] = __float_as_uint(Ks[(ni * 8 + g) * LK + kc * 8 + t    ]);
                bb[1] = __float_as_uint(Ks[(ni * 8 + g) * LK + kc * 8 + t + 4]);
                mma_m16n8k8(sf[ni], qf[kc], bb, sf[ni]);
            }
        }

        // ---- online softmax (rows g and g+8; quad = 4 lanes share a row)
        float mx0 = -INFINITY, mx1 = -INFINITY;
        #pragma unroll
        for (int ni = 0; ni < 8; ni++) {
            mx0 = fmaxf(mx0, fmaxf(sf[ni][0], sf[ni][1]));
            mx1 = fmaxf(mx1, fmaxf(sf[ni][2], sf[ni][3]));
        }
        mx0 = fmaxf(mx0, __shfl_xor_sync(0xffffffffu, mx0, 1));
        mx0 = fmaxf(mx0, __shfl_xor_sync(0xffffffffu, mx0, 2));
        mx1 = fmaxf(mx1, __shfl_xor_sync(0xffffffffu, mx1, 1));
        mx1 = fmaxf(mx1, __shfl_xor_sync(0xffffffffu, mx1, 2));

        const float nm0 = fmaxf(m0v, mx0);
        const float nm1 = fmaxf(m1v, mx1);
        float sum0 = 0.f, sum1 = 0.f;
        #pragma unroll
        for (int ni = 0; ni < 8; ni++) {
            float p0 = __expf(sf[ni][0] - nm0);
            float p1 = __expf(sf[ni][1] - nm0);
            float p2 = __expf(sf[ni][2] - nm1);
            float p3 = __expf(sf[ni][3] - nm1);
            sf[ni][0] = p0; sf[ni][1] = p1; sf[ni][2] = p2; sf[ni][3] = p3;
            sum0 += p0 + p1; sum1 += p2 + p3;
        }
        sum0 += __shfl_xor_sync(0xffffffffu, sum0, 1);
        sum0 += __shfl_xor_sync(0xffffffffu, sum0, 2);
        sum1 += __shfl_xor_sync(0xffffffffu, sum1, 1);
        sum1 += __shfl_xor_sync(0xffffffffu, sum1, 2);

        const float f0 = __expf(m0v - nm0);
        const float f1 = __expf(m1v - nm1);
        l0v = l0v * f0 + sum0;  m0v = nm0;
        l1v = l1v * f1 + sum1;  m1v = nm1;
        #pragma unroll
        for (int ni = 0; ni < 8; ni++) {
            oacc[ni][0] *= f0; oacc[ni][1] *= f0;
            oacc[ni][2] *= f1; oacc[ni][3] *= f1;
        }

        // ---- write P (tf32) to per-warp smem
        #pragma unroll
        for (int ni = 0; ni < 8; ni++) {
            Pw[ g      * LP + ni * 8 + 2 * t    ] = f2tf(sf[ni][0]);
            Pw[ g      * LP + ni * 8 + 2 * t + 1] = f2tf(sf[ni][1]);
            Pw[(g + 8) * LP + ni * 8 + 2 * t    ] = f2tf(sf[ni][2]);
            Pw[(g + 8) * LP + ni * 8 + 2 * t + 1] = f2tf(sf[ni][3]);
        }
        __syncwarp();

        // ---- O += P @ V
        #pragma unroll
        for (int kc = 0; kc < 8; kc++) {
            uint32_t af[4];
            af[0] = __float_as_uint(Pw[ g      * LP + kc * 8 + t    ]);
            af[1] = __float_as_uint(Pw[(g + 8) * LP + kc * 8 + t    ]);
            af[2] = __float_as_uint(Pw[ g      * LP + kc * 8 + t + 4]);
            af[3] = __float_as_uint(Pw[(g + 8) * LP + kc * 8 + t + 4]);
            #pragma unroll
            for (int ni = 0; ni < 8; ni++) {
                uint32_t bb[2];
                bb[0] = __float_as_uint(Vs[(kc * 8 + t    ) * LV + ni * 8 + g]);
                bb[1] = __float_as_uint(Vs[(kc * 8 + t + 4) * LV + ni * 8 + g]);
                mma_m16n8k8(oacc[ni], af, bb, oacc[ni]);
            }
        }
        __syncthreads();
    }

    // ---- epilogue: normalize and write to g_attn[b][s][h*64+dd]
    const int b = bh >> 4, h = bh & 15;
    const int row0 = q0 + wid * 16 + g;
    const int row1 = row0 + 8;
    const float inv0 = 1.f / l0v, inv1 = 1.f / l1v;
    #pragma unroll
    for (int ni = 0; ni < 8; ni++) {
        const int col = h * HD + ni * 8 + 2 * t;
        *(float2*)&g_attn[((size_t)(b * S_ + row0)) * D_ + col] =
            make_float2(oacc[ni][0] * inv0, oacc[ni][1] * inv0);
        *(float2*)&g_attn[((size_t)(b * S_ + row1)) * D_ + col] =
            make_float2(oacc[ni][2] * inv1, oacc[ni][3] * inv1);
    }
}

// ---------------- launch ----------------------------------------------------
extern "C" void kernel_launch(void* const* d_in, const int* in_sizes, int n_in,
                              void* d_out, int out_size)
{
    const float* x      = (const float*)d_in[0];
    const float* W_qkv  = (const float*)d_in[1];
    const float* b_qkv  = (const float*)d_in[2];
    const float* W_proj = (const float*)d_in[3];
    const float* b_proj = (const float*)d_in[4];
    float* out = (float*)d_out;

    cudaFuncSetAttribute(attn_tc, cudaFuncAttributeMaxDynamicSharedMemorySize, ATTN_SMEM);

    // 1) QKV GEMM -> scatter tf32 Q(pre-scaled)/K/V in [B,H,S,64]
    gemm_tc<1, 0><<<dim3(3 * D_ / BN, ROWS / BM), 256>>>(
        x, W_qkv, b_qkv, nullptr, ROWS, 3 * D_, D_);

    // 2) flash attention
    attn_tc<<<dim3(S_ / 64, B_ * H_), 128, ATTN_SMEM>>>();

    // 3) output projection
    gemm_tc<0, 1><<<dim3(D_ / BN, ROWS / BM), 256>>>(
        nullptr, W_proj, b_proj, out, ROWS, D_, D_);
}

// round 3
// speedup vs baseline: 3.3924x; 1.4204x over previous
#include <cuda_runtime.h>
#include <math.h>
#include <stdint.h>

#define B_  4
#define S_  2048
#define D_  1024
#define H_  16
#define HD  64
#define ROWS (B_*S_)        // 8192
#define SCALE 0.125f        // 64^-0.5

// ---------------- scratch (device globals; no allocations) ----------------
__device__ float g_q[(size_t)B_*H_*S_*HD];     // [B*H, S, 64]  (pre-scaled, tf32)
__device__ float g_k[(size_t)B_*H_*S_*HD];     // tf32-rounded
__device__ float g_v[(size_t)B_*H_*S_*HD];     // tf32-rounded
__device__ float g_attn[(size_t)ROWS*D_];      // [B*S, D] fp32

// ---------------- helpers ---------------------------------------------------
__device__ __forceinline__ float f2tf(float x) {
    uint32_t u; asm("cvt.rna.tf32.f32 %0, %1;" : "=r"(u) : "f"(x));
    return __uint_as_float(u);
}
__device__ __forceinline__ uint32_t ldtf(const float* p) {
    uint32_t u; asm("cvt.rna.tf32.f32 %0, %1;" : "=r"(u) : "f"(*p));
    return u;
}
__device__ __forceinline__ void cp16(void* dst, const void* src) {
    uint32_t d = (uint32_t)__cvta_generic_to_shared(dst);
    asm volatile("cp.async.ca.shared.global [%0], [%1], 16;\n" :: "r"(d), "l"(src));
}
#define CP_COMMIT() asm volatile("cp.async.commit_group;\n" ::: "memory")
#define CP_WAIT0()  asm volatile("cp.async.wait_group 0;\n" ::: "memory")

__device__ __forceinline__ void mma_m16n8k8(float d[4], const uint32_t a[4],
                                            const uint32_t b[2], const float c[4]) {
    asm volatile(
        "mma.sync.aligned.m16n8k8.row.col.f32.tf32.tf32.f32 "
        "{%0,%1,%2,%3}, {%4,%5,%6,%7}, {%8,%9}, {%10,%11,%12,%13};"
        : "=f"(d[0]), "=f"(d[1]), "=f"(d[2]), "=f"(d[3])
        : "r"(a[0]), "r"(a[1]), "r"(a[2]), "r"(a[3]),
          "r"(b[0]), "r"(b[1]),
          "f"(c[0]), "f"(c[1]), "f"(c[2]), "f"(c[3]));
}

// ---------------- tensor-core GEMM: C = A[M,K] @ W[K,N] + bias --------------
// 128x128x32 tiles, 2-stage cp.async, 256 threads (8 warps 2x4), warp 64x32.
#define BM 128
#define BN 128
#define BK 32
#define PA 36     // As pitch (floats): banks 4g+t -> conflict free, 144B row
#define PB 136    // Bs pitch: banks 8t+g -> conflict free, 544B row
#define GEMM_SMEM ((2*BM*PA + 2*BK*PB) * (int)sizeof(float))   // 71680 B

template<int SCATTER, int A_GATTN>
__global__ void __launch_bounds__(256, 2) gemm_tc(
    const float* __restrict__ Ain, const float* __restrict__ W,
    const float* __restrict__ bias, float* __restrict__ C,
    int M, int N, int K)
{
    const float* A = A_GATTN ? g_attn : Ain;

    extern __shared__ float sm[];
    float* As[2] = { sm, sm + BM * PA };
    float* Bs[2] = { sm + 2 * BM * PA, sm + 2 * BM * PA + BK * PB };

    const int tid  = threadIdx.x;
    const int lane = tid & 31;
    const int wid  = tid >> 5;
    const int g    = lane >> 2;
    const int t    = lane & 3;
    const int wm   = (wid & 1) * 64;
    const int wn   = (wid >> 1) * 32;
    const int m0   = blockIdx.y * BM;
    const int n0   = blockIdx.x * BN;

    float acc[4][4][4];
    #pragma unroll
    for (int mi = 0; mi < 4; mi++)
        #pragma unroll
        for (int ni = 0; ni < 4; ni++)
            #pragma unroll
            for (int j = 0; j < 4; j++) acc[mi][ni][j] = 0.f;

    // staging: A 128x32 fp32 = 1024 16B chunks; B 32x128 = 1024 chunks
    auto stage = [&](int s, int k0) {
        #pragma unroll
        for (int p = 0; p < 4; p++) {
            const int idx  = p * 256 + tid;
            const int arow = idx >> 3;
            const int acol = (idx & 7) * 4;
            cp16(&As[s][arow * PA + acol], &A[(size_t)(m0 + arow) * K + k0 + acol]);
        }
        #pragma unroll
        for (int p = 0; p < 4; p++) {
            const int idx  = p * 256 + tid;
            const int brow = idx >> 5;
            const int bcol = (idx & 31) * 4;
            cp16(&Bs[s][brow * PB + bcol], &W[(size_t)(k0 + brow) * N + n0 + bcol]);
        }
        CP_COMMIT();
    };

    const int NT = K / BK;
    stage(0, 0);

    for (int it = 0; it < NT; it++) {
        CP_WAIT0();
        __syncthreads();
        if (it + 1 < NT) stage((it + 1) & 1, (it + 1) * BK);

        const float* as = As[it & 1];
        const float* bs = Bs[it & 1];

        #pragma unroll
        for (int ks = 0; ks < 4; ks++) {
            const int kb = ks * 8;
            uint32_t af[4][4], bf[4][2];
            #pragma unroll
            for (int mi = 0; mi < 4; mi++) {
                const int mr = wm + mi * 16;
                af[mi][0] = ldtf(&as[(mr + g    ) * PA + kb + t    ]);
                af[mi][1] = ldtf(&as[(mr + g + 8) * PA + kb + t    ]);
                af[mi][2] = ldtf(&as[(mr + g    ) * PA + kb + t + 4]);
                af[mi][3] = ldtf(&as[(mr + g + 8) * PA + kb + t + 4]);
            }
            #pragma unroll
            for (int ni = 0; ni < 4; ni++) {
                const int nc = wn + ni * 8;
                bf[ni][0] = ldtf(&bs[(kb + t    ) * PB + nc + g]);
                bf[ni][1] = ldtf(&bs[(kb + t + 4) * PB + nc + g]);
            }
            #pragma unroll
            for (int mi = 0; mi < 4; mi++)
                #pragma unroll
                for (int ni = 0; ni < 4; ni++)
                    mma_m16n8k8(acc[mi][ni], af[mi], bf[ni], acc[mi][ni]);
        }
        __syncthreads();
    }

    // epilogue
    #pragma unroll
    for (int mi = 0; mi < 4; mi++) {
        const int r0 = m0 + wm + mi * 16 + g;
        #pragma unroll
        for (int ni = 0; ni < 4; ni++) {
            const int c0 = n0 + wn + ni * 8 + 2 * t;
            float v0 = acc[mi][ni][0] + bias[c0];
            float v1 = acc[mi][ni][1] + bias[c0 + 1];
            float v2 = acc[mi][ni][2] + bias[c0];
            float v3 = acc[mi][ni][3] + bias[c0 + 1];
            if (SCATTER) {
                const int sect = c0 >> 10;
                const int rem  = c0 & 1023;
                const int h    = rem >> 6;
                const int dd   = rem & 63;
                float* dst = (sect == 0) ? g_q : (sect == 1) ? g_k : g_v;
                const float sc = (sect == 0) ? SCALE : 1.f;
                {
                    const int b = r0 >> 11, s = r0 & 2047;
                    float* p = &dst[(((size_t)(b * H_ + h) * S_) + s) * HD + dd];
                    p[0] = f2tf(v0 * sc);
                    p[1] = f2tf(v1 * sc);
                }
                {
                    const int r1 = r0 + 8;
                    const int b = r1 >> 11, s = r1 & 2047;
                    float* p = &dst[(((size_t)(b * H_ + h) * S_) + s) * HD + dd];
                    p[0] = f2tf(v2 * sc);
                    p[1] = f2tf(v3 * sc);
                }
            } else {
                *(float2*)&C[(size_t)r0 * N + c0]       = make_float2(v0, v1);
                *(float2*)&C[(size_t)(r0 + 8) * N + c0] = make_float2(v2, v3);
            }
        }
    }
}

// ---------------- flash attention (tensor core, 128q, double-buffered) ------
// 256 threads (8 warps); 128 query rows (16/warp); 64-key tiles, 2-stage KV.
#define LKA 68    // K pitch: banks 4g+t conflict-free; 272B row (16B mult)
#define LVA 72    // V pitch: banks 8t+g conflict-free; 288B row
#define LPA 68    // P per-warp pitch
#define ATTN_FLOATS (2*64*LKA + 2*64*LVA + 8*16*LPA)
#define ATTN_SMEM (ATTN_FLOATS * (int)sizeof(float))   // 106496 B

__global__ void __launch_bounds__(256, 2) attn_tc()
{
    extern __shared__ float sm[];
    float* Ks[2] = { sm, sm + 64 * LKA };
    float* Vs[2] = { sm + 2 * 64 * LKA, sm + 2 * 64 * LKA + 64 * LVA };
    float* Ps    = sm + 2 * 64 * LKA + 2 * 64 * LVA;

    const int tid  = threadIdx.x;
    const int lane = tid & 31;
    const int wid  = tid >> 5;
    const int g    = lane >> 2;
    const int t    = lane & 3;
    const int q0   = blockIdx.x * 128;
    const int bh   = blockIdx.y;

    const float* Qb = g_q + (size_t)bh * S_ * HD;
    const float* Kb = g_k + (size_t)bh * S_ * HD;
    const float* Vb = g_v + (size_t)bh * S_ * HD;

    // ---- stage Q (128x64) into Ks[0](rows 0-63) + Ks[1](rows 64-127)
    #pragma unroll
    for (int p = 0; p < 8; p++) {
        const int idx = p * 256 + tid;
        const int row = idx >> 4;
        const int ch  = (idx & 15) * 4;
        float4 v = *(const float4*)&Qb[(size_t)(q0 + row) * HD + ch];
        float* d = &Ks[row >> 6][(row & 63) * LKA + ch];
        d[0] = v.x; d[1] = v.y; d[2] = v.z; d[3] = v.w;
    }
    __syncthreads();

    // lift Q fragments (already tf32 + pre-scaled)
    uint32_t qf[8][4];
    {
        const float* qsrc = Ks[wid >> 2];
        const int r0 = (wid * 16) & 63;
        #pragma unroll
        for (int kc = 0; kc < 8; kc++) {
            qf[kc][0] = __float_as_uint(qsrc[(r0 + g    ) * LKA + kc * 8 + t    ]);
            qf[kc][1] = __float_as_uint(qsrc[(r0 + g + 8) * LKA + kc * 8 + t    ]);
            qf[kc][2] = __float_as_uint(qsrc[(r0 + g    ) * LKA + kc * 8 + t + 4]);
            qf[kc][3] = __float_as_uint(qsrc[(r0 + g + 8) * LKA + kc * 8 + t + 4]);
        }
    }
    __syncthreads();

    auto stage_kv = [&](int s, int kb) {
        #pragma unroll
        for (int p = 0; p < 4; p++) {
            const int idx = p * 256 + tid;
            const int row = idx >> 4;
            const int ch  = (idx & 15) * 4;
            cp16(&Ks[s][row * LKA + ch], &Kb[(size_t)(kb + row) * HD + ch]);
            cp16(&Vs[s][row * LVA + ch], &Vb[(size_t)(kb + row) * HD + ch]);
        }
        CP_COMMIT();
    };

    float oacc[8][4];
    #pragma unroll
    for (int ni = 0; ni < 8; ni++)
        #pragma unroll
        for (int j = 0; j < 4; j++) oacc[ni][j] = 0.f;
    float m0v = -INFINITY, m1v = -INFINITY, l0v = 0.f, l1v = 0.f;

    float* Pw = Ps + wid * 16 * LPA;

    stage_kv(0, 0);

    for (int kt = 0; kt < S_ / 64; kt++) {
        CP_WAIT0();
        __syncthreads();
        if (kt + 1 < S_ / 64) stage_kv((kt + 1) & 1, (kt + 1) * 64);

        const float* ks = Ks[kt & 1];
        const float* vs = Vs[kt & 1];

        // ---- S = Q @ K^T
        float sf[8][4];
        #pragma unroll
        for (int ni = 0; ni < 8; ni++)
            #pragma unroll
            for (int j = 0; j < 4; j++) sf[ni][j] = 0.f;

        #pragma unroll
        for (int kc = 0; kc < 8; kc++) {
            #pragma unroll
            for (int ni = 0; ni < 8; ni++) {
                uint32_t bb[2];
                bb[0] = __float_as_uint(ks[(ni * 8 + g) * LKA + kc * 8 + t    ]);
                bb[1] = __float_as_uint(ks[(ni * 8 + g) * LKA + kc * 8 + t + 4]);
                mma_m16n8k8(sf[ni], qf[kc], bb, sf[ni]);
            }
        }

        // ---- online softmax (rows g, g+8; quads share rows)
        float mx0 = -INFINITY, mx1 = -INFINITY;
        #pragma unroll
        for (int ni = 0; ni < 8; ni++) {
            mx0 = fmaxf(mx0, fmaxf(sf[ni][0], sf[ni][1]));
            mx1 = fmaxf(mx1, fmaxf(sf[ni][2], sf[ni][3]));
        }
        mx0 = fmaxf(mx0, __shfl_xor_sync(0xffffffffu, mx0, 1));
        mx0 = fmaxf(mx0, __shfl_xor_sync(0xffffffffu, mx0, 2));
        mx1 = fmaxf(mx1, __shfl_xor_sync(0xffffffffu, mx1, 1));
        mx1 = fmaxf(mx1, __shfl_xor_sync(0xffffffffu, mx1, 2));

        const float nm0 = fmaxf(m0v, mx0);
        const float nm1 = fmaxf(m1v, mx1);
        float sum0 = 0.f, sum1 = 0.f;
        #pragma unroll
        for (int ni = 0; ni < 8; ni++) {
            float p0 = __expf(sf[ni][0] - nm0);
            float p1 = __expf(sf[ni][1] - nm0);
            float p2 = __expf(sf[ni][2] - nm1);
            float p3 = __expf(sf[ni][3] - nm1);
            sf[ni][0] = p0; sf[ni][1] = p1; sf[ni][2] = p2; sf[ni][3] = p3;
            sum0 += p0 + p1; sum1 += p2 + p3;
        }
        sum0 += __shfl_xor_sync(0xffffffffu, sum0, 1);
        sum0 += __shfl_xor_sync(0xffffffffu, sum0, 2);
        sum1 += __shfl_xor_sync(0xffffffffu, sum1, 1);
        sum1 += __shfl_xor_sync(0xffffffffu, sum1, 2);

        const float f0 = __expf(m0v - nm0);
        const float f1 = __expf(m1v - nm1);
        l0v = l0v * f0 + sum0;  m0v = nm0;
        l1v = l1v * f1 + sum1;  m1v = nm1;
        #pragma unroll
        for (int ni = 0; ni < 8; ni++) {
            oacc[ni][0] *= f0; oacc[ni][1] *= f0;
            oacc[ni][2] *= f1; oacc[ni][3] *= f1;
        }

        // ---- write P (tf32) to per-warp smem
        #pragma unroll
        for (int ni = 0; ni < 8; ni++) {
            Pw[ g      * LPA + ni * 8 + 2 * t    ] = f2tf(sf[ni][0]);
            Pw[ g      * LPA + ni * 8 + 2 * t + 1] = f2tf(sf[ni][1]);
            Pw[(g + 8) * LPA + ni * 8 + 2 * t    ] = f2tf(sf[ni][2]);
            Pw[(g + 8) * LPA + ni * 8 + 2 * t + 1] = f2tf(sf[ni][3]);
        }
        __syncwarp();

        // ---- O += P @ V
        #pragma unroll
        for (int kc = 0; kc < 8; kc++) {
            uint32_t af[4];
            af[0] = __float_as_uint(Pw[ g      * LPA + kc * 8 + t    ]);
            af[1] = __float_as_uint(Pw[(g + 8) * LPA + kc * 8 + t    ]);
            af[2] = __float_as_uint(Pw[ g      * LPA + kc * 8 + t + 4]);
            af[3] = __float_as_uint(Pw[(g + 8) * LPA + kc * 8 + t + 4]);
            #pragma unroll
            for (int ni = 0; ni < 8; ni++) {
                uint32_t bb[2];
                bb[0] = __float_as_uint(vs[(kc * 8 + t    ) * LVA + ni * 8 + g]);
                bb[1] = __float_as_uint(vs[(kc * 8 + t + 4) * LVA + ni * 8 + g]);
                mma_m16n8k8(oacc[ni], af, bb, oacc[ni]);
            }
        }
        __syncthreads();
    }

    // ---- epilogue
    const int b = bh >> 4, h = bh & 15;
    const int row0 = q0 + wid * 16 + g;
    const int row1 = row0 + 8;
    const float inv0 = 1.f / l0v, inv1 = 1.f / l1v;
    #pragma unroll
    for (int ni = 0; ni < 8; ni++) {
        const int col = h * HD + ni * 8 + 2 * t;
        *(float2*)&g_attn[((size_t)(b * S_ + row0)) * D_ + col] =
            make_float2(oacc[ni][0] * inv0, oacc[ni][1] * inv0);
        *(float2*)&g_attn[((size_t)(b * S_ + row1)) * D_ + col] =
            make_float2(oacc[ni][2] * inv1, oacc[ni][3] * inv1);
    }
}

// ---------------- launch ----------------------------------------------------
extern "C" void kernel_launch(void* const* d_in, const int* in_sizes, int n_in,
                              void* d_out, int out_size)
{
    const float* x      = (const float*)d_in[0];
    const float* W_qkv  = (const float*)d_in[1];
    const float* b_qkv  = (const float*)d_in[2];
    const float* W_proj = (const float*)d_in[3];
    const float* b_proj = (const float*)d_in[4];
    float* out = (float*)d_out;

    cudaFuncSetAttribute(gemm_tc<1, 0>, cudaFuncAttributeMaxDynamicSharedMemorySize, GEMM_SMEM);
    cudaFuncSetAttribute(gemm_tc<0, 1>, cudaFuncAttributeMaxDynamicSharedMemorySize, GEMM_SMEM);
    cudaFuncSetAttribute(attn_tc, cudaFuncAttributeMaxDynamicSharedMemorySize, ATTN_SMEM);

    // 1) QKV GEMM -> scatter tf32 Q(pre-scaled)/K/V in [B,H,S,64]
    gemm_tc<1, 0><<<dim3(3 * D_ / BN, ROWS / BM), 256, GEMM_SMEM>>>(
        x, W_qkv, b_qkv, nullptr, ROWS, 3 * D_, D_);

    // 2) flash attention (128 q-rows per block)
    attn_tc<<<dim3(S_ / 128, B_ * H_), 256, ATTN_SMEM>>>();

    // 3) output projection
    gemm_tc<0, 1><<<dim3(D_ / BN, ROWS / BM), 256, GEMM_SMEM>>>(
        nullptr, W_proj, b_proj, out, ROWS, D_, D_);
}

// round 6
// speedup vs baseline: 8.5768x; 2.5282x over previous
#include <cuda_runtime.h>
#include <cuda_fp16.h>
#include <math.h>
#include <stdint.h>

#define B_  4
#define S_  2048
#define D_  1024
#define H_  16
#define HD  64
#define ROWS (B_*S_)        // 8192
#define SCALE 0.125f        // 64^-0.5

// ---------------- scratch (device globals; no allocations) ----------------
__device__ __half g_q[(size_t)B_*H_*S_*HD];     // [B*H, S, 64] half (Q pre-scaled)
__device__ __half g_k[(size_t)B_*H_*S_*HD];
__device__ __half g_v[(size_t)B_*H_*S_*HD];
__device__ __half g_attnh[(size_t)ROWS*D_];     // attention out, half
__device__ __half g_xh[(size_t)ROWS*D_];        // x in half
__device__ __half g_wqkvh[(size_t)D_*3*D_];     // W_qkv half (row-major [K][N])
__device__ __half g_wprojh[(size_t)D_*D_];      // W_proj half

// ---------------- helpers ---------------------------------------------------
__global__ void conv_half(const float* __restrict__ s, __half* __restrict__ d, int n) {
    int i = (blockIdx.x * blockDim.x + threadIdx.x) * 4;
    if (i < n) {
        float4 v = *(const float4*)(s + i);
        __half2* p = (__half2*)(d + i);
        p[0] = __floats2half2_rn(v.x, v.y);
        p[1] = __floats2half2_rn(v.z, v.w);
    }
}

__device__ __forceinline__ void cp16(void* dst, const void* src) {
    uint32_t d = (uint32_t)__cvta_generic_to_shared(dst);
    asm volatile("cp.async.ca.shared.global [%0], [%1], 16;\n" :: "r"(d), "l"(src));
}
#define CP_COMMIT() asm volatile("cp.async.commit_group;\n" ::: "memory")
#define CP_WAIT0()  asm volatile("cp.async.wait_group 0;\n" ::: "memory")

__device__ __forceinline__ void ldsm4(uint32_t r[4], uint32_t a) {
    asm volatile("ldmatrix.sync.aligned.m8n8.x4.shared.b16 {%0,%1,%2,%3}, [%4];"
        : "=r"(r[0]), "=r"(r[1]), "=r"(r[2]), "=r"(r[3]) : "r"(a));
}
__device__ __forceinline__ void ldsm4t(uint32_t r[4], uint32_t a) {
    asm volatile("ldmatrix.sync.aligned.m8n8.x4.trans.shared.b16 {%0,%1,%2,%3}, [%4];"
        : "=r"(r[0]), "=r"(r[1]), "=r"(r[2]), "=r"(r[3]) : "r"(a));
}
__device__ __forceinline__ void mma16816(float d[4], const uint32_t a[4],
                                         const uint32_t b[2], const float c[4]) {
    asm volatile(
        "mma.sync.aligned.m16n8k16.row.col.f32.f16.f16.f32 "
        "{%0,%1,%2,%3}, {%4,%5,%6,%7}, {%8,%9}, {%10,%11,%12,%13};"
        : "=f"(d[0]), "=f"(d[1]), "=f"(d[2]), "=f"(d[3])
        : "r"(a[0]), "r"(a[1]), "r"(a[2]), "r"(a[3]),
          "r"(b[0]), "r"(b[1]),
          "f"(c[0]), "f"(c[1]), "f"(c[2]), "f"(c[3]));
}

// ---------------- fp16 tensor-core GEMM: C = A[M,K] @ W[K,N] + bias ---------
// 128x128x64 tiles, 2-stage cp.async, 256 threads (8 warps 2x4), warp 64x32.
// A row-major [m][k] (non-trans LDSM); W row-major [k][n] (trans LDSM).
#define BM 128
#define BN 128
#define BK 64
#define PAH 72     // A pitch in halves (144B row: 16B-mult, LDSM conflict-free)
#define PBH 136    // B pitch in halves (272B row)
#define GEMM_SMEM ((2*BM*PAH + 2*BK*PBH) * 2)   // 71680 B

template<int SCATTER>
__global__ void __launch_bounds__(256, 2) gemm_h(
    const __half* __restrict__ A, const __half* __restrict__ W,
    const float* __restrict__ bias, float* __restrict__ C,
    int M, int N, int K)
{
    extern __shared__ __half smh[];
    __half* As[2] = { smh, smh + BM * PAH };
    __half* Bs[2] = { smh + 2 * BM * PAH, smh + 2 * BM * PAH + BK * PBH };
    const uint32_t sbase = (uint32_t)__cvta_generic_to_shared(smh);
    const uint32_t aoff[2] = { 0u, (uint32_t)(BM * PAH * 2) };
    const uint32_t boff[2] = { (uint32_t)(2 * BM * PAH * 2),
                               (uint32_t)(2 * BM * PAH * 2 + BK * PBH * 2) };

    const int tid  = threadIdx.x;
    const int lane = tid & 31;
    const int wid  = tid >> 5;
    const int g    = lane >> 2;
    const int t    = lane & 3;
    const int wm   = (wid & 1) * 64;
    const int wn   = (wid >> 1) * 32;
    const int m0   = blockIdx.y * BM;
    const int n0   = blockIdx.x * BN;

    // LDSM per-lane address components (in halves)
    const int a_row = lane & 15;            // A/non-trans A-operand
    const int a_cg  = (lane >> 4) * 8;
    const int bt_row = lane & 15;           // trans B-operand: rows = k
    const int bt_cg  = (lane >> 4) * 8;     // n col-group

    float acc[4][4][4];
    #pragma unroll
    for (int mi = 0; mi < 4; mi++)
        #pragma unroll
        for (int ni = 0; ni < 4; ni++)
            #pragma unroll
            for (int j = 0; j < 4; j++) acc[mi][ni][j] = 0.f;

    auto stage = [&](int s, int k0) {
        #pragma unroll
        for (int p = 0; p < 4; p++) {       // A: 128 rows x 64 halves
            const int idx = p * 256 + tid;
            const int row = idx >> 3;
            const int ch  = (idx & 7) * 8;
            cp16(&As[s][row * PAH + ch], &A[(size_t)(m0 + row) * K + k0 + ch]);
        }
        #pragma unroll
        for (int p = 0; p < 4; p++) {       // B: 64 rows x 128 halves
            const int idx = p * 256 + tid;
            const int row = idx >> 4;
            const int ch  = (idx & 15) * 8;
            cp16(&Bs[s][row * PBH + ch], &W[(size_t)(k0 + row) * N + n0 + ch]);
        }
        CP_COMMIT();
    };

    const int NT = K / BK;
    stage(0, 0);

    for (int it = 0; it < NT; it++) {
        CP_WAIT0();
        __syncthreads();
        if (it + 1 < NT) stage((it + 1) & 1, (it + 1) * BK);

        const uint32_t ab = sbase + aoff[it & 1];
        const uint32_t bb = sbase + boff[it & 1];

        #pragma unroll
        for (int ks = 0; ks < 4; ks++) {
            uint32_t af[4][4], bf[2][4];
            #pragma unroll
            for (int mi = 0; mi < 4; mi++)
                ldsm4(af[mi], ab + (uint32_t)(((wm + mi * 16 + a_row) * PAH
                                               + ks * 16 + a_cg) * 2));
            #pragma unroll
            for (int pr = 0; pr < 2; pr++)
                ldsm4t(bf[pr], bb + (uint32_t)(((ks * 16 + bt_row) * PBH
                                                + wn + pr * 16 + bt_cg) * 2));
            #pragma unroll
            for (int mi = 0; mi < 4; mi++)
                #pragma unroll
                for (int ni = 0; ni < 4; ni++)
                    mma16816(acc[mi][ni], af[mi], &bf[ni >> 1][(ni & 1) * 2],
                             acc[mi][ni]);
        }
    }

    // epilogue
    #pragma unroll
    for (int mi = 0; mi < 4; mi++) {
        const int r0 = m0 + wm + mi * 16 + g;
        #pragma unroll
        for (int ni = 0; ni < 4; ni++) {
            const int c0 = n0 + wn + ni * 8 + 2 * t;
            float v0 = acc[mi][ni][0] + bias[c0];
            float v1 = acc[mi][ni][1] + bias[c0 + 1];
            float v2 = acc[mi][ni][2] + bias[c0];
            float v3 = acc[mi][ni][3] + bias[c0 + 1];
            if (SCATTER) {
                const int sect = c0 >> 10;
                const int rem  = c0 & 1023;
                const int h    = rem >> 6;
                const int dd   = rem & 63;
                __half* dst = (sect == 0) ? g_q : (sect == 1) ? g_k : g_v;
                const float sc = (sect == 0) ? SCALE : 1.f;
                {
                    const int b = r0 >> 11, s = r0 & 2047;
                    *(__half2*)&dst[(((size_t)(b * H_ + h) * S_) + s) * HD + dd] =
                        __floats2half2_rn(v0 * sc, v1 * sc);
                }
                {
                    const int r1 = r0 + 8;
                    const int b = r1 >> 11, s = r1 & 2047;
                    *(__half2*)&dst[(((size_t)(b * H_ + h) * S_) + s) * HD + dd] =
                        __floats2half2_rn(v2 * sc, v3 * sc);
                }
            } else {
                *(float2*)&C[(size_t)r0 * N + c0]       = make_float2(v0, v1);
                *(float2*)&C[(size_t)(r0 + 8) * N + c0] = make_float2(v2, v3);
            }
        }
    }
}

// ---------------- flash attention (fp16 mma, 128q, double-buffered) ---------
#define LKH 72
// halves: K 2x64x72, V 2x64x72, P 8x16x72
#define OFF_K0 0
#define OFF_K1 (64*LKH)
#define OFF_V0 (2*64*LKH)
#define OFF_V1 (3*64*LKH)
#define OFF_P  (4*64*LKH)
#define ATTN_SMEM ((4*64*LKH + 8*16*LKH) * 2)   // 55296 B

__global__ void __launch_bounds__(256, 2) attn_h()
{
    extern __shared__ __half smh[];
    const uint32_t sbase = (uint32_t)__cvta_generic_to_shared(smh);
    __half* Ks[2] = { smh + OFF_K0, smh + OFF_K1 };
    __half* Vs[2] = { smh + OFF_V0, smh + OFF_V1 };

    const int tid  = threadIdx.x;
    const int lane = tid & 31;
    const int wid  = tid >> 5;
    const int g    = lane >> 2;
    const int t    = lane & 3;
    const int q0   = blockIdx.x * 128;
    const int bh   = blockIdx.y;

    const __half* Qb = g_q + (size_t)bh * S_ * HD;
    const __half* Kb = g_k + (size_t)bh * S_ * HD;
    const __half* Vb = g_v + (size_t)bh * S_ * HD;

    // LDSM lane address components
    const int a_row  = lane & 15;                        // A-operand (Q, P)
    const int a_cg   = (lane >> 4) * 8;
    const int bn_row = (lane & 7) + ((lane & 16) >> 1);  // non-trans B (K)
    const int bn_cg  = (lane & 8);
    const int bt_row = lane & 15;                        // trans B (V)
    const int bt_cg  = (lane >> 4) * 8;

    // ---- stage Q (128x64) into K buffers, lift to fragments
    #pragma unroll
    for (int p = 0; p < 4; p++) {
        const int idx = p * 256 + tid;
        const int row = idx >> 3;             // 0..127
        const int ch  = (idx & 7) * 8;
        cp16(&smh[(row >> 6) * OFF_K1 + (row & 63) * LKH + ch],
             &Qb[(size_t)(q0 + row) * HD + ch]);
    }
    CP_COMMIT();
    CP_WAIT0();
    __syncthreads();

    uint32_t qf[4][4];
    {
        const uint32_t qb = sbase + (uint32_t)(((wid >> 2) * OFF_K1
                              + ((wid & 3) * 16 + a_row) * LKH) * 2);
        #pragma unroll
        for (int kc = 0; kc < 4; kc++)
            ldsm4(qf[kc], qb + (uint32_t)((kc * 16 + a_cg) * 2));
    }
    __syncthreads();

    auto stage_kv = [&](int s, int kb) {
        #pragma unroll
        for (int p = 0; p < 2; p++) {
            const int idx = p * 256 + tid;
            const int row = idx >> 3;         // 0..63
            const int ch  = (idx & 7) * 8;
            cp16(&Ks[s][row * LKH + ch], &Kb[(size_t)(kb + row) * HD + ch]);
            cp16(&Vs[s][row * LKH + ch], &Vb[(size_t)(kb + row) * HD + ch]);
        }
        CP_COMMIT();
    };

    float oacc[8][4];
    #pragma unroll
    for (int ni = 0; ni < 8; ni++)
        #pragma unroll
        for (int j = 0; j < 4; j++) oacc[ni][j] = 0.f;
    float m0v = -INFINITY, m1v = -INFINITY, l0v = 0.f, l1v = 0.f;

    __half* Pw = smh + OFF_P + wid * 16 * LKH;
    const uint32_t pwb = sbase + (uint32_t)((OFF_P + wid * 16 * LKH) * 2);

    stage_kv(0, 0);

    for (int kt = 0; kt < S_ / 64; kt++) {
        CP_WAIT0();
        __syncthreads();
        if (kt + 1 < S_ / 64) stage_kv((kt + 1) & 1, (kt + 1) * 64);

        const uint32_t kcur = sbase + (uint32_t)(((kt & 1) ? OFF_K1 : OFF_K0) * 2);
        const uint32_t vcur = sbase + (uint32_t)(((kt & 1) ? OFF_V1 : OFF_V0) * 2);

        // ---- S = Q @ K^T
        float sf[8][4];
        #pragma unroll
        for (int ni = 0; ni < 8; ni++)
            #pragma unroll
            for (int j = 0; j < 4; j++) sf[ni][j] = 0.f;

        #pragma unroll
        for (int kc = 0; kc < 4; kc++) {
            #pragma unroll
            for (int np = 0; np < 4; np++) {
                uint32_t kf[4];
                ldsm4(kf, kcur + (uint32_t)(((np * 16 + bn_row) * LKH
                                             + kc * 16 + bn_cg) * 2));
                mma16816(sf[np * 2    ], qf[kc], &kf[0], sf[np * 2    ]);
                mma16816(sf[np * 2 + 1], qf[kc], &kf[2], sf[np * 2 + 1]);
            }
        }

        // ---- online softmax (rows g, g+8)
        float mx0 = -INFINITY, mx1 = -INFINITY;
        #pragma unroll
        for (int ni = 0; ni < 8; ni++) {
            mx0 = fmaxf(mx0, fmaxf(sf[ni][0], sf[ni][1]));
            mx1 = fmaxf(mx1, fmaxf(sf[ni][2], sf[ni][3]));
        }
        mx0 = fmaxf(mx0, __shfl_xor_sync(0xffffffffu, mx0, 1));
        mx0 = fmaxf(mx0, __shfl_xor_sync(0xffffffffu, mx0, 2));
        mx1 = fmaxf(mx1, __shfl_xor_sync(0xffffffffu, mx1, 1));
        mx1 = fmaxf(mx1, __shfl_xor_sync(0xffffffffu, mx1, 2));

        const float nm0 = fmaxf(m0v, mx0);
        const float nm1 = fmaxf(m1v, mx1);
        float sum0 = 0.f, sum1 = 0.f;
        #pragma unroll
        for (int ni = 0; ni < 8; ni++) {
            float p0 = __expf(sf[ni][0] - nm0);
            float p1 = __expf(sf[ni][1] - nm0);
            float p2 = __expf(sf[ni][2] - nm1);
            float p3 = __expf(sf[ni][3] - nm1);
            sf[ni][0] = p0; sf[ni][1] = p1; sf[ni][2] = p2; sf[ni][3] = p3;
            sum0 += p0 + p1; sum1 += p2 + p3;
        }
        sum0 += __shfl_xor_sync(0xffffffffu, sum0, 1);
        sum0 += __shfl_xor_sync(0xffffffffu, sum0, 2);
        sum1 += __shfl_xor_sync(0xffffffffu, sum1, 1);
        sum1 += __shfl_xor_sync(0xffffffffu, sum1, 2);

        const float f0 = __expf(m0v - nm0);
        const float f1 = __expf(m1v - nm1);
        l0v = l0v * f0 + sum0;  m0v = nm0;
        l1v = l1v * f1 + sum1;  m1v = nm1;
        #pragma unroll
        for (int ni = 0; ni < 8; ni++) {
            oacc[ni][0] *= f0; oacc[ni][1] *= f0;
            oacc[ni][2] *= f1; oacc[ni][3] *= f1;
        }

        // ---- write P (half2) to per-warp smem
        #pragma unroll
        for (int ni = 0; ni < 8; ni++) {
            *(__half2*)&Pw[ g      * LKH + ni * 8 + 2 * t] =
                __floats2half2_rn(sf[ni][0], sf[ni][1]);
            *(__half2*)&Pw[(g + 8) * LKH + ni * 8 + 2 * t] =
                __floats2half2_rn(sf[ni][2], sf[ni][3]);
        }
        __syncwarp();

        // ---- O += P @ V
        #pragma unroll
        for (int kc = 0; kc < 4; kc++) {
            uint32_t pf[4];
            ldsm4(pf, pwb + (uint32_t)((a_row * LKH + kc * 16 + a_cg) * 2));
            #pragma unroll
            for (int np = 0; np < 4; np++) {
                uint32_t vf[4];
                ldsm4t(vf, vcur + (uint32_t)(((kc * 16 + bt_row) * LKH
                                              + np * 16 + bt_cg) * 2));
                mma16816(oacc[np * 2    ], pf, &vf[0], oacc[np * 2    ]);
                mma16816(oacc[np * 2 + 1], pf, &vf[2], oacc[np * 2 + 1]);
            }
        }
    }

    // ---- epilogue: normalize, write half to g_attnh[b][s][h*64+dd]
    const int b = bh >> 4, h = bh & 15;
    const int row0 = q0 + wid * 16 + g;
    const int row1 = row0 + 8;
    const float inv0 = 1.f / l0v, inv1 = 1.f / l1v;
    #pragma unroll
    for (int ni = 0; ni < 8; ni++) {
        const int col = h * HD + ni * 8 + 2 * t;
        *(__half2*)&g_attnh[((size_t)(b * S_ + row0)) * D_ + col] =
            __floats2half2_rn(oacc[ni][0] * inv0, oacc[ni][1] * inv0);
        *(__half2*)&g_attnh[((size_t)(b * S_ + row1)) * D_ + col] =
            __floats2half2_rn(oacc[ni][2] * inv1, oacc[ni][3] * inv1);
    }
}

// ---------------- launch ----------------------------------------------------
extern "C" void kernel_launch(void* const* d_in, const int* in_sizes, int n_in,
                              void* d_out, int out_size)
{
    const float* x      = (const float*)d_in[0];
    const float* W_qkv  = (const float*)d_in[1];
    const float* b_qkv  = (const float*)d_in[2];
    const float* W_proj = (const float*)d_in[3];
    const float* b_proj = (const float*)d_in[4];
    float* out = (float*)d_out;

    cudaFuncSetAttribute(gemm_h<1>, cudaFuncAttributeMaxDynamicSharedMemorySize, GEMM_SMEM);
    cudaFuncSetAttribute(gemm_h<0>, cudaFuncAttributeMaxDynamicSharedMemorySize, GEMM_SMEM);
    cudaFuncSetAttribute(attn_h, cudaFuncAttributeMaxDynamicSharedMemorySize, ATTN_SMEM);

    __half *xh, *wqkvh, *wprojh, *qh, *kh, *vh, *attnh;
    cudaGetSymbolAddress((void**)&xh, g_xh);
    cudaGetSymbolAddress((void**)&wqkvh, g_wqkvh);
    cudaGetSymbolAddress((void**)&wprojh, g_wprojh);
    cudaGetSymbolAddress((void**)&attnh, g_attnh);
    (void)qh; (void)kh; (void)vh;

    // 0) fp32 -> fp16 converts
    conv_half<<<(ROWS * D_ / 4 + 255) / 256, 256>>>(x, xh, ROWS * D_);
    conv_half<<<(D_ * 3 * D_ / 4 + 255) / 256, 256>>>(W_qkv, wqkvh, D_ * 3 * D_);
    conv_half<<<(D_ * D_ / 4 + 255) / 256, 256>>>(W_proj, wprojh, D_ * D_);

    // 1) QKV GEMM -> scatter half Q(pre-scaled)/K/V in [B,H,S,64]
    gemm_h<1><<<dim3(3 * D_ / BN, ROWS / BM), 256, GEMM_SMEM>>>(
        xh, wqkvh, b_qkv, nullptr, ROWS, 3 * D_, D_);

    // 2) flash attention (128 q-rows per block)
    attn_h<<<dim3(S_ / 128, B_ * H_), 256, ATTN_SMEM>>>();

    // 3) output projection (fp32 out)
    gemm_h<0><<<dim3(D_ / BN, ROWS / BM), 256, GEMM_SMEM>>>(
        attnh, wprojh, b_proj, out, ROWS, D_, D_);
}

// round 15
// speedup vs baseline: 9.0336x; 1.0533x over previous
#include <cuda_runtime.h>
#include <cuda_fp16.h>
#include <math.h>
#include <stdint.h>

#define B_  4
#define S_  2048
#define D_  1024
#define H_  16
#define HD  64
#define ROWS (B_*S_)        // 8192
#define SCALE 0.125f        // 64^-0.5

// ---------------- scratch (device globals; no allocations) ----------------
__device__ __half g_q[(size_t)B_*H_*S_*HD];     // [B*H, S, 64] half (Q pre-scaled)
__device__ __half g_k[(size_t)B_*H_*S_*HD];
__device__ __half g_v[(size_t)B_*H_*S_*HD];
__device__ __half g_attnh[(size_t)ROWS*D_];     // attention out, half
__device__ __half g_xh[(size_t)ROWS*D_];        // x in half
__device__ __half g_wqkvh[(size_t)D_*3*D_];     // W_qkv half (row-major [K][N])
__device__ __half g_wprojh[(size_t)D_*D_];      // W_proj half

// ---------------- helpers ---------------------------------------------------
__global__ void conv_half(const float* __restrict__ s, __half* __restrict__ d, int n) {
    int i = (blockIdx.x * blockDim.x + threadIdx.x) * 4;
    if (i < n) {
        float4 v = *(const float4*)(s + i);
        __half2* p = (__half2*)(d + i);
        p[0] = __floats2half2_rn(v.x, v.y);
        p[1] = __floats2half2_rn(v.z, v.w);
    }
}

__device__ __forceinline__ void cp16(void* dst, const void* src) {
    uint32_t d = (uint32_t)__cvta_generic_to_shared(dst);
    asm volatile("cp.async.ca.shared.global [%0], [%1], 16;\n" :: "r"(d), "l"(src));
}
#define CP_COMMIT() asm volatile("cp.async.commit_group;\n" ::: "memory")
#define CP_WAIT0()  asm volatile("cp.async.wait_group 0;\n" ::: "memory")

__device__ __forceinline__ void ldsm4(uint32_t r[4], uint32_t a) {
    asm volatile("ldmatrix.sync.aligned.m8n8.x4.shared.b16 {%0,%1,%2,%3}, [%4];"
        : "=r"(r[0]), "=r"(r[1]), "=r"(r[2]), "=r"(r[3]) : "r"(a));
}
__device__ __forceinline__ void ldsm4t(uint32_t r[4], uint32_t a) {
    asm volatile("ldmatrix.sync.aligned.m8n8.x4.trans.shared.b16 {%0,%1,%2,%3}, [%4];"
        : "=r"(r[0]), "=r"(r[1]), "=r"(r[2]), "=r"(r[3]) : "r"(a));
}
__device__ __forceinline__ void mma16816(float d[4], const uint32_t a[4],
                                         const uint32_t b[2], const float c[4]) {
    asm volatile(
        "mma.sync.aligned.m16n8k16.row.col.f32.f16.f16.f32 "
        "{%0,%1,%2,%3}, {%4,%5,%6,%7}, {%8,%9}, {%10,%11,%12,%13};"
        : "=f"(d[0]), "=f"(d[1]), "=f"(d[2]), "=f"(d[3])
        : "r"(a[0]), "r"(a[1]), "r"(a[2]), "r"(a[3]),
          "r"(b[0]), "r"(b[1]),
          "f"(c[0]), "f"(c[1]), "f"(c[2]), "f"(c[3]));
}
__device__ __forceinline__ uint32_t packh2(float a, float b) {
    __half2 h = __floats2half2_rn(a, b);
    return *(uint32_t*)&h;
}

// ---------------- fp16 tensor-core GEMM: C = A[M,K] @ W[K,N] + bias ---------
// 128x128x64 tiles, 2-stage cp.async, 256 threads (8 warps 2x4), warp 64x32.
#define BM 128
#define BN 128
#define BK 64
#define PAH 72     // A pitch in halves (144B row)
#define PBH 136    // B pitch in halves (272B row)
#define GEMM_SMEM ((2*BM*PAH + 2*BK*PBH) * 2)   // 71680 B

template<int SCATTER>
__global__ void __launch_bounds__(256, 2) gemm_h(
    const __half* __restrict__ A, const __half* __restrict__ W,
    const float* __restrict__ bias, float* __restrict__ C,
    int M, int N, int K)
{
    extern __shared__ __half smh[];
    __half* As[2] = { smh, smh + BM * PAH };
    __half* Bs[2] = { smh + 2 * BM * PAH, smh + 2 * BM * PAH + BK * PBH };
    const uint32_t sbase = (uint32_t)__cvta_generic_to_shared(smh);
    const uint32_t aoff[2] = { 0u, (uint32_t)(BM * PAH * 2) };
    const uint32_t boff[2] = { (uint32_t)(2 * BM * PAH * 2),
                               (uint32_t)(2 * BM * PAH * 2 + BK * PBH * 2) };

    const int tid  = threadIdx.x;
    const int lane = tid & 31;
    const int wid  = tid >> 5;
    const int g    = lane >> 2;
    const int t    = lane & 3;
    const int wm   = (wid & 1) * 64;
    const int wn   = (wid >> 1) * 32;
    const int m0   = blockIdx.y * BM;
    const int n0   = blockIdx.x * BN;

    const int a_row = lane & 15;
    const int a_cg  = (lane >> 4) * 8;
    const int bt_row = lane & 15;
    const int bt_cg  = (lane >> 4) * 8;

    float acc[4][4][4];
    #pragma unroll
    for (int mi = 0; mi < 4; mi++)
        #pragma unroll
        for (int ni = 0; ni < 4; ni++)
            #pragma unroll
            for (int j = 0; j < 4; j++) acc[mi][ni][j] = 0.f;

    auto stage = [&](int s, int k0) {
        #pragma unroll
        for (int p = 0; p < 4; p++) {       // A: 128 rows x 64 halves
            const int idx = p * 256 + tid;
            const int row = idx >> 3;
            const int ch  = (idx & 7) * 8;
            cp16(&As[s][row * PAH + ch], &A[(size_t)(m0 + row) * K + k0 + ch]);
        }
        #pragma unroll
        for (int p = 0; p < 4; p++) {       // B: 64 rows x 128 halves
            const int idx = p * 256 + tid;
            const int row = idx >> 4;
            const int ch  = (idx & 15) * 8;
            cp16(&Bs[s][row * PBH + ch], &W[(size_t)(k0 + row) * N + n0 + ch]);
        }
        CP_COMMIT();
    };

    const int NT = K / BK;
    stage(0, 0);

    for (int it = 0; it < NT; it++) {
        CP_WAIT0();
        __syncthreads();
        if (it + 1 < NT) stage((it + 1) & 1, (it + 1) * BK);

        const uint32_t ab = sbase + aoff[it & 1];
        const uint32_t bb = sbase + boff[it & 1];

        #pragma unroll
        for (int ks = 0; ks < 4; ks++) {
            uint32_t af[4][4], bf[2][4];
            #pragma unroll
            for (int mi = 0; mi < 4; mi++)
                ldsm4(af[mi], ab + (uint32_t)(((wm + mi * 16 + a_row) * PAH
                                               + ks * 16 + a_cg) * 2));
            #pragma unroll
            for (int pr = 0; pr < 2; pr++)
                ldsm4t(bf[pr], bb + (uint32_t)(((ks * 16 + bt_row) * PBH
                                                + wn + pr * 16 + bt_cg) * 2));
            #pragma unroll
            for (int mi = 0; mi < 4; mi++)
                #pragma unroll
                for (int ni = 0; ni < 4; ni++)
                    mma16816(acc[mi][ni], af[mi], &bf[ni >> 1][(ni & 1) * 2],
                             acc[mi][ni]);
        }
    }

    // epilogue
    #pragma unroll
    for (int mi = 0; mi < 4; mi++) {
        const int r0 = m0 + wm + mi * 16 + g;
        #pragma unroll
        for (int ni = 0; ni < 4; ni++) {
            const int c0 = n0 + wn + ni * 8 + 2 * t;
            float v0 = acc[mi][ni][0] + bias[c0];
            float v1 = acc[mi][ni][1] + bias[c0 + 1];
            float v2 = acc[mi][ni][2] + bias[c0];
            float v3 = acc[mi][ni][3] + bias[c0 + 1];
            if (SCATTER) {
                const int sect = c0 >> 10;
                const int rem  = c0 & 1023;
                const int h    = rem >> 6;
                const int dd   = rem & 63;
                __half* dst = (sect == 0) ? g_q : (sect == 1) ? g_k : g_v;
                const float sc = (sect == 0) ? SCALE : 1.f;
                {
                    const int b = r0 >> 11, s = r0 & 2047;
                    *(__half2*)&dst[(((size_t)(b * H_ + h) * S_) + s) * HD + dd] =
                        __floats2half2_rn(v0 * sc, v1 * sc);
                }
                {
                    const int r1 = r0 + 8;
                    const int b = r1 >> 11, s = r1 & 2047;
                    *(__half2*)&dst[(((size_t)(b * H_ + h) * S_) + s) * HD + dd] =
                        __floats2half2_rn(v2 * sc, v3 * sc);
                }
            } else {
                *(float2*)&C[(size_t)r0 * N + c0]       = make_float2(v0, v1);
                *(float2*)&C[(size_t)(r0 + 8) * N + c0] = make_float2(v2, v3);
            }
        }
    }
}

// ---------------- flash attention (fp16 mma, P kept in registers) -----------
// 256 threads (8 warps); 128 q-rows (16/warp); 64-key tiles, 2-stage KV.
// The QK^T C-fragment layout == PV A-operand layout, so P never hits smem.
#define LKH 72
#define OFF_K0 0
#define OFF_K1 (64*LKH)
#define OFF_V0 (2*64*LKH)
#define OFF_V1 (3*64*LKH)
#define ATTN_SMEM ((4*64*LKH) * 2)   // 36864 B

__global__ void __launch_bounds__(256, 2) attn_h()
{
    extern __shared__ __half smh[];
    const uint32_t sbase = (uint32_t)__cvta_generic_to_shared(smh);
    __half* Ks[2] = { smh + OFF_K0, smh + OFF_K1 };
    __half* Vs[2] = { smh + OFF_V0, smh + OFF_V1 };

    const int tid  = threadIdx.x;
    const int lane = tid & 31;
    const int wid  = tid >> 5;
    const int g    = lane >> 2;
    const int t    = lane & 3;
    const int q0   = blockIdx.x * 128;
    const int bh   = blockIdx.y;

    const __half* Qb = g_q + (size_t)bh * S_ * HD;
    const __half* Kb = g_k + (size_t)bh * S_ * HD;
    const __half* Vb = g_v + (size_t)bh * S_ * HD;

    const int a_row  = lane & 15;                        // A-operand (Q)
    const int a_cg   = (lane >> 4) * 8;
    const int bn_row = (lane & 7) + ((lane & 16) >> 1);  // non-trans B (K)
    const int bn_cg  = (lane & 8);
    const int bt_row = lane & 15;                        // trans B (V)
    const int bt_cg  = (lane >> 4) * 8;

    // ---- stage Q (128x64) into K buffers, lift to fragments
    #pragma unroll
    for (int p = 0; p < 4; p++) {
        const int idx = p * 256 + tid;
        const int row = idx >> 3;             // 0..127
        const int ch  = (idx & 7) * 8;
        cp16(&smh[(row >> 6) * OFF_K1 + (row & 63) * LKH + ch],
             &Qb[(size_t)(q0 + row) * HD + ch]);
    }
    CP_COMMIT();
    CP_WAIT0();
    __syncthreads();

    uint32_t qf[4][4];
    {
        const uint32_t qb = sbase + (uint32_t)(((wid >> 2) * OFF_K1
                              + ((wid & 3) * 16 + a_row) * LKH) * 2);
        #pragma unroll
        for (int kc = 0; kc < 4; kc++)
            ldsm4(qf[kc], qb + (uint32_t)((kc * 16 + a_cg) * 2));
    }
    __syncthreads();

    auto stage_kv = [&](int s, int kb) {
        #pragma unroll
        for (int p = 0; p < 2; p++) {
            const int idx = p * 256 + tid;
            const int row = idx >> 3;         // 0..63
            const int ch  = (idx & 7) * 8;
            cp16(&Ks[s][row * LKH + ch], &Kb[(size_t)(kb + row) * HD + ch]);
            cp16(&Vs[s][row * LKH + ch], &Vb[(size_t)(kb + row) * HD + ch]);
        }
        CP_COMMIT();
    };

    float oacc[8][4];
    #pragma unroll
    for (int ni = 0; ni < 8; ni++)
        #pragma unroll
        for (int j = 0; j < 4; j++) oacc[ni][j] = 0.f;
    float m0v = -INFINITY, m1v = -INFINITY, l0v = 0.f, l1v = 0.f;

    stage_kv(0, 0);

    for (int kt = 0; kt < S_ / 64; kt++) {
        CP_WAIT0();
        __syncthreads();
        if (kt + 1 < S_ / 64) stage_kv((kt + 1) & 1, (kt + 1) * 64);

        const uint32_t kcur = sbase + (uint32_t)(((kt & 1) ? OFF_K1 : OFF_K0) * 2);
        const uint32_t vcur = sbase + (uint32_t)(((kt & 1) ? OFF_V1 : OFF_V0) * 2);

        // ---- S = Q @ K^T
        float sf[8][4];
        #pragma unroll
        for (int ni = 0; ni < 8; ni++)
            #pragma unroll
            for (int j = 0; j < 4; j++) sf[ni][j] = 0.f;

        #pragma unroll
        for (int kc = 0; kc < 4; kc++) {
            #pragma unroll
            for (int np = 0; np < 4; np++) {
                uint32_t kf[4];
                ldsm4(kf, kcur + (uint32_t)(((np * 16 + bn_row) * LKH
                                             + kc * 16 + bn_cg) * 2));
                mma16816(sf[np * 2    ], qf[kc], &kf[0], sf[np * 2    ]);
                mma16816(sf[np * 2 + 1], qf[kc], &kf[2], sf[np * 2 + 1]);
            }
        }

        // ---- online softmax (rows g, g+8; quads share rows)
        float mx0 = -INFINITY, mx1 = -INFINITY;
        #pragma unroll
        for (int ni = 0; ni < 8; ni++) {
            mx0 = fmaxf(mx0, fmaxf(sf[ni][0], sf[ni][1]));
            mx1 = fmaxf(mx1, fmaxf(sf[ni][2], sf[ni][3]));
        }
        mx0 = fmaxf(mx0, __shfl_xor_sync(0xffffffffu, mx0, 1));
        mx0 = fmaxf(mx0, __shfl_xor_sync(0xffffffffu, mx0, 2));
        mx1 = fmaxf(mx1, __shfl_xor_sync(0xffffffffu, mx1, 1));
        mx1 = fmaxf(mx1, __shfl_xor_sync(0xffffffffu, mx1, 2));

        const float nm0 = fmaxf(m0v, mx0);
        const float nm1 = fmaxf(m1v, mx1);
        float sum0 = 0.f, sum1 = 0.f;
        uint32_t pf[4][4];   // A-operand fragments of P, packed in registers
        #pragma unroll
        for (int ni = 0; ni < 8; ni++) {
            float p0 = __expf(sf[ni][0] - nm0);
            float p1 = __expf(sf[ni][1] - nm0);
            float p2 = __expf(sf[ni][2] - nm1);
            float p3 = __expf(sf[ni][3] - nm1);
            sum0 += p0 + p1; sum1 += p2 + p3;
            // C-frag (rows g/g+8, cols 2t,2t+1) == A-frag regs for k16 chunk ni/2
            pf[ni >> 1][(ni & 1) * 2    ] = packh2(p0, p1);
            pf[ni >> 1][(ni & 1) * 2 + 1] = packh2(p2, p3);
        }
        sum0 += __shfl_xor_sync(0xffffffffu, sum0, 1);
        sum0 += __shfl_xor_sync(0xffffffffu, sum0, 2);
        sum1 += __shfl_xor_sync(0xffffffffu, sum1, 1);
        sum1 += __shfl_xor_sync(0xffffffffu, sum1, 2);

        const float f0 = __expf(m0v - nm0);
        const float f1 = __expf(m1v - nm1);
        l0v = l0v * f0 + sum0;  m0v = nm0;
        l1v = l1v * f1 + sum1;  m1v = nm1;
        #pragma unroll
        for (int ni = 0; ni < 8; ni++) {
            oacc[ni][0] *= f0; oacc[ni][1] *= f0;
            oacc[ni][2] *= f1; oacc[ni][3] *= f1;
        }

        // ---- O += P @ V  (P fragments straight from registers)
        #pragma unroll
        for (int kc = 0; kc < 4; kc++) {
            #pragma unroll
            for (int np = 0; np < 4; np++) {
                uint32_t vf[4];
                ldsm4t(vf, vcur + (uint32_t)(((kc * 16 + bt_row) * LKH
                                              + np * 16 + bt_cg) * 2));
                mma16816(oacc[np * 2    ], pf[kc], &vf[0], oacc[np * 2    ]);
                mma16816(oacc[np * 2 + 1], pf[kc], &vf[2], oacc[np * 2 + 1]);
            }
        }
    }

    // ---- epilogue: normalize, write half to g_attnh[b][s][h*64+dd]
    const int b = bh >> 4, h = bh & 15;
    const int row0 = q0 + wid * 16 + g;
    const int row1 = row0 + 8;
    const float inv0 = 1.f / l0v, inv1 = 1.f / l1v;
    #pragma unroll
    for (int ni = 0; ni < 8; ni++) {
        const int col = h * HD + ni * 8 + 2 * t;
        *(__half2*)&g_attnh[((size_t)(b * S_ + row0)) * D_ + col] =
            __floats2half2_rn(oacc[ni][0] * inv0, oacc[ni][1] * inv0);
        *(__half2*)&g_attnh[((size_t)(b * S_ + row1)) * D_ + col] =
            __floats2half2_rn(oacc[ni][2] * inv1, oacc[ni][3] * inv1);
    }
}

// ---------------- launch ----------------------------------------------------
extern "C" void kernel_launch(void* const* d_in, const int* in_sizes, int n_in,
                              void* d_out, int out_size)
{
    const float* x      = (const float*)d_in[0];
    const float* W_qkv  = (const float*)d_in[1];
    const float* b_qkv  = (const float*)d_in[2];
    const float* W_proj = (const float*)d_in[3];
    const float* b_proj = (const float*)d_in[4];
    float* out = (float*)d_out;

    cudaFuncSetAttribute(gemm_h<1>, cudaFuncAttributeMaxDynamicSharedMemorySize, GEMM_SMEM);
    cudaFuncSetAttribute(gemm_h<0>, cudaFuncAttributeMaxDynamicSharedMemorySize, GEMM_SMEM);
    cudaFuncSetAttribute(attn_h, cudaFuncAttributeMaxDynamicSharedMemorySize, ATTN_SMEM);

    __half *xh, *wqkvh, *wprojh, *attnh;
    cudaGetSymbolAddress((void**)&xh, g_xh);
    cudaGetSymbolAddress((void**)&wqkvh, g_wqkvh);
    cudaGetSymbolAddress((void**)&wprojh, g_wprojh);
    cudaGetSymbolAddress((void**)&attnh, g_attnh);

    // 0) fp32 -> fp16 converts
    conv_half<<<(ROWS * D_ / 4 + 255) / 256, 256>>>(x, xh, ROWS * D_);
    conv_half<<<(D_ * 3 * D_ / 4 + 255) / 256, 256>>>(W_qkv, wqkvh, D_ * 3 * D_);
    conv_half<<<(D_ * D_ / 4 + 255) / 256, 256>>>(W_proj, wprojh, D_ * D_);

    // 1) QKV GEMM -> scatter half Q(pre-scaled)/K/V in [B,H,S,64]
    gemm_h<1><<<dim3(3 * D_ / BN, ROWS / BM), 256, GEMM_SMEM>>>(
        xh, wqkvh, b_qkv, nullptr, ROWS, 3 * D_, D_);

    // 2) flash attention (P register-resident)
    attn_h<<<dim3(S_ / 128, B_ * H_), 256, ATTN_SMEM>>>();

    // 3) output projection (fp32 out)
    gemm_h<0><<<dim3(D_ / BN, ROWS / BM), 256, GEMM_SMEM>>>(
        attnh, wprojh, b_proj, out, ROWS, D_, D_);
}